// round 14
// baseline (speedup 1.0000x reference)
#include <cuda_runtime.h>
#include <cuda_bf16.h>
#include <cstdint>
#include <math.h>
#include <math_constants.h>

#define B_ 4
#define S_ 2048
#define D_ 1024
#define M_ (B_*S_)

typedef __nv_bfloat16 bf16;

// Scratch --------------------------------------------------------------------
__device__ __align__(256) bf16 g_xh[M_*D_], g_xl[M_*D_];
__device__ __align__(256) bf16 g_wvh[D_*D_], g_wvl[D_*D_];
__device__ __align__(256) bf16 g_qh[M_*D_], g_ql[M_*D_];
__device__ __align__(256) bf16 g_kh[M_*D_], g_kl[M_*D_];
__device__ __align__(256) bf16 g_vh[M_*D_], g_vl[M_*D_];
__device__ __align__(256) float g_s[(size_t)B_*S_*S_];
__device__ __align__(256) bf16 g_ph[(size_t)B_*S_*S_], g_pl[(size_t)B_*S_*S_];
// int8 slices + row scales for Q/K projections
__device__ __align__(256) int8_t g_xa0[M_*D_],  g_xa1[M_*D_];
__device__ __align__(256) int8_t g_wqa0[D_*D_], g_wqa1[D_*D_];
__device__ __align__(256) int8_t g_wka0[D_*D_], g_wka1[D_*D_];
__device__ __align__(256) float  g_sx[M_], g_swq[D_], g_swk[D_];

__device__ const int d_pv_by[24]    = {15,15,7,14,14,13,13,6,12,12,11,11,5,10,10,9,9,4,8,8,3,2,1,0};
__device__ const int d_pv_piece[24] = { 0, 1,-1, 0, 1, 0, 1,-1, 0, 1, 0, 1,-1, 0, 1,0,1,-1,0,1,-1,-1,-1,-1};

#define LDBT_S 136
#define STG 33792u
#define OFF_AH(s) ((s)*STG)
#define OFF_AL(s) ((s)*STG + 8192u)
#define OFF_BH(s) ((s)*STG + 16384u)
#define OFF_BL(s) ((s)*STG + 25088u)
#define SMEM_TOTAL (3*33792)
#define SMEM_I8 (3*12288)
#define NTHR 256

__device__ __forceinline__ uint32_t swz(int r, int k) {
    return (uint32_t)(r * 64 + ((((k >> 3) ^ ((r >> 1) & 3)) << 4) | ((k & 7) << 1)));
}
// int8 tiles: 32B rows. 16B-unit swizzle, conflict-free for cp.async + ldmatrix.
__device__ __forceinline__ uint32_t swz8(int r, int h) {
    return (uint32_t)(((r >> 2) << 7) + ((((r & 3) << 1) | (h ^ ((r >> 2) & 1))) << 4));
}
__device__ __forceinline__ uint32_t smem_u32(const void* p) {
    uint32_t a;
    asm("{ .reg .u64 t; cvta.to.shared.u64 t, %1; cvt.u32.u64 %0, t; }" : "=r"(a) : "l"(p));
    return a;
}
__device__ __forceinline__ void cpa16(uint32_t s, const void* g) {
    asm volatile("cp.async.cg.shared.global [%0], [%1], 16;" :: "r"(s), "l"(g));
}
__device__ __forceinline__ void ldm_x4(uint32_t addr, uint32_t r[4]) {
    asm volatile("ldmatrix.sync.aligned.m8n8.x4.shared.b16 {%0,%1,%2,%3}, [%4];"
        : "=r"(r[0]), "=r"(r[1]), "=r"(r[2]), "=r"(r[3]) : "r"(addr));
}
__device__ __forceinline__ void ldm_x4_t(uint32_t addr, uint32_t r[4]) {
    asm volatile("ldmatrix.sync.aligned.m8n8.x4.trans.shared.b16 {%0,%1,%2,%3}, [%4];"
        : "=r"(r[0]), "=r"(r[1]), "=r"(r[2]), "=r"(r[3]) : "r"(addr));
}
__device__ __forceinline__ void mma16816(float c[4], const uint32_t a[4], const uint32_t b[2]) {
    asm volatile("mma.sync.aligned.m16n8k16.row.col.f32.bf16.bf16.f32 "
        "{%0,%1,%2,%3}, {%4,%5,%6,%7}, {%8,%9}, {%0,%1,%2,%3};"
        : "+f"(c[0]), "+f"(c[1]), "+f"(c[2]), "+f"(c[3])
        : "r"(a[0]), "r"(a[1]), "r"(a[2]), "r"(a[3]), "r"(b[0]), "r"(b[1]));
}
__device__ __forceinline__ void mma_s8(int c[4], const uint32_t a[4], const uint32_t b[2]) {
    asm volatile("mma.sync.aligned.m16n8k32.row.col.s32.s8.s8.s32 "
        "{%0,%1,%2,%3}, {%4,%5,%6,%7}, {%8,%9}, {%0,%1,%2,%3};"
        : "+r"(c[0]), "+r"(c[1]), "+r"(c[2]), "+r"(c[3])
        : "r"(a[0]), "r"(a[1]), "r"(a[2]), "r"(a[3]), "r"(b[0]), "r"(b[1]));
}

// ===================== bf16 engine (sv / pv) ================================
template<int BT>
__device__ __forceinline__ void load_stage(uint32_t sb, int st, int tid,
    const bf16* __restrict__ Ah, const bf16* __restrict__ Al, int lda,
    const bf16* __restrict__ Bh, const bf16* __restrict__ Bl, int ldb, int k0)
{
    #pragma unroll
    for (int it = 0; it < 2; ++it) {
        int c = tid + it * NTHR;
        int row = c >> 2;
        int kc  = (c & 3) << 3;
        uint32_t so = swz(row, kc);
        cpa16(sb + OFF_AH(st) + so, Ah + (size_t)row * lda + k0 + kc);
        cpa16(sb + OFF_AL(st) + so, Al + (size_t)row * lda + k0 + kc);
        if (BT == 0) {
            cpa16(sb + OFF_BH(st) + so, Bh + (size_t)row * ldb + k0 + kc);
            cpa16(sb + OFF_BL(st) + so, Bl + (size_t)row * ldb + k0 + kc);
        } else {
            int br = c >> 4;
            int bn = (c & 15) << 3;
            uint32_t bo = (uint32_t)((br * LDBT_S + bn) * 2);
            cpa16(sb + OFF_BH(st) + bo, Bh + (size_t)(k0 + br) * ldb + bn);
            cpa16(sb + OFF_BL(st) + bo, Bl + (size_t)(k0 + br) * ldb + bn);
        }
    }
}

template<int BT>
__device__ __forceinline__ void compute_stage(uint32_t sb, int st, int lane,
                                              int wm, int wn, float acc[4][4][4])
{
    const uint32_t sAh = sb + OFF_AH(st), sAl = sb + OFF_AL(st);
    const uint32_t sBh = sb + OFF_BH(st), sBl = sb + OFF_BL(st);
    #pragma unroll
    for (int ks = 0; ks < 2; ++ks) {
        uint32_t bh[4][2], bl[4][2];
        if (BT == 0) {
            int nr = (lane & 7) + ((lane >> 4) & 1) * 8;
            int kh = ks * 16 + ((lane >> 3) & 1) * 8;
            #pragma unroll
            for (int np = 0; np < 2; ++np) {
                uint32_t off = swz(wn * 32 + np * 16 + nr, kh);
                uint32_t r[4];
                ldm_x4(sBh + off, r);
                bh[2*np][0]=r[0]; bh[2*np][1]=r[1]; bh[2*np+1][0]=r[2]; bh[2*np+1][1]=r[3];
                ldm_x4(sBl + off, r);
                bl[2*np][0]=r[0]; bl[2*np][1]=r[1]; bl[2*np+1][0]=r[2]; bl[2*np+1][1]=r[3];
            }
        } else {
            int kr = ks * 16 + ((lane >> 3) & 1) * 8 + (lane & 7);
            int nh = ((lane >> 4) & 1) * 8;
            #pragma unroll
            for (int np = 0; np < 2; ++np) {
                uint32_t off = (uint32_t)((kr * LDBT_S + wn * 32 + np * 16 + nh) * 2);
                uint32_t r[4];
                ldm_x4_t(sBh + off, r);
                bh[2*np][0]=r[0]; bh[2*np][1]=r[1]; bh[2*np+1][0]=r[2]; bh[2*np+1][1]=r[3];
                ldm_x4_t(sBl + off, r);
                bl[2*np][0]=r[0]; bl[2*np][1]=r[1]; bl[2*np+1][0]=r[2]; bl[2*np+1][1]=r[3];
            }
        }
        const int arow = wm * 64 + (lane & 15);
        const int akh  = ks * 16 + (lane >> 4) * 8;
        #pragma unroll
        for (int mi = 0; mi < 4; ++mi) {
            uint32_t ah[4], al[4];
            uint32_t off = swz(arow + mi * 16, akh);
            ldm_x4(sAh + off, ah);
            ldm_x4(sAl + off, al);
            #pragma unroll
            for (int ni = 0; ni < 4; ++ni) {
                mma16816(acc[mi][ni], ah, bh[ni]);
                mma16816(acc[mi][ni], ah, bl[ni]);
                mma16816(acc[mi][ni], al, bh[ni]);
            }
        }
    }
}

template<int BT>
__device__ __forceinline__ void gemm_run(uint32_t sb,
    const bf16* __restrict__ Ah, const bf16* __restrict__ Al, int lda,
    const bf16* __restrict__ Bh, const bf16* __restrict__ Bl, int ldb,
    int niter, float acc[4][4][4])
{
    const int tid = threadIdx.x, lane = tid & 31, wid = tid >> 5;
    const int wm = wid & 1, wn = wid >> 1;
    #pragma unroll
    for (int mi = 0; mi < 4; ++mi)
        #pragma unroll
        for (int ni = 0; ni < 4; ++ni)
            #pragma unroll
            for (int j = 0; j < 4; ++j) acc[mi][ni][j] = 0.f;

    load_stage<BT>(sb, 0, tid, Ah, Al, lda, Bh, Bl, ldb, 0);
    asm volatile("cp.async.commit_group;" ::: "memory");
    load_stage<BT>(sb, 1, tid, Ah, Al, lda, Bh, Bl, ldb, 32);
    asm volatile("cp.async.commit_group;" ::: "memory");
    int st = 0;
    for (int i = 0; i < niter; ++i) {
        if (i + 1 < niter) asm volatile("cp.async.wait_group 1;" ::: "memory");
        else               asm volatile("cp.async.wait_group 0;" ::: "memory");
        __syncthreads();
        if (i + 2 < niter) {
            int slot = st + 2 >= 3 ? st - 1 : st + 2;
            load_stage<BT>(sb, slot, tid, Ah, Al, lda, Bh, Bl, ldb, (i + 2) * 32);
            asm volatile("cp.async.commit_group;" ::: "memory");
        }
        compute_stage<BT>(sb, st, lane, wm, wn, acc);
        st = (st == 2) ? 0 : st + 1;
    }
}

__device__ __forceinline__ void epi_bf16_split(float acc[4][4][4], int by, int bx,
                                               bf16* Oh, bf16* Ol)
{
    const int tid = threadIdx.x, lane = tid & 31, wid = tid >> 5;
    const int wm = wid & 1, wn = wid >> 1;
    #pragma unroll
    for (int mi = 0; mi < 4; ++mi)
        #pragma unroll
        for (int ni = 0; ni < 4; ++ni) {
            int r0 = by * 128 + wm * 64 + mi * 16 + (lane >> 2);
            int c0 = bx * 128 + wn * 32 + ni * 8 + (lane & 3) * 2;
            #pragma unroll
            for (int half = 0; half < 2; ++half) {
                int gr = r0 + half * 8;
                float v0 = acc[mi][ni][half * 2 + 0];
                float v1 = acc[mi][ni][half * 2 + 1];
                bf16 h0 = __float2bfloat16(v0); bf16 l0 = __float2bfloat16(v0 - __bfloat162float(h0));
                bf16 h1 = __float2bfloat16(v1); bf16 l1 = __float2bfloat16(v1 - __bfloat162float(h1));
                *reinterpret_cast<__nv_bfloat162*>(Oh + (size_t)gr * D_ + c0) = __halves2bfloat162(h0, h1);
                *reinterpret_cast<__nv_bfloat162*>(Ol + (size_t)gr * D_ + c0) = __halves2bfloat162(l0, l1);
            }
        }
}

__device__ __forceinline__ void epi_f32_tile(float acc[4][4][4], float* dst)
{
    const int tid = threadIdx.x, lane = tid & 31, wid = tid >> 5;
    const int wm = wid & 1, wn = wid >> 1;
    #pragma unroll
    for (int mi = 0; mi < 4; ++mi)
        #pragma unroll
        for (int ni = 0; ni < 4; ++ni) {
            int rl = wm * 64 + mi * 16 + (lane >> 2);
            int cl = wn * 32 + ni * 8 + (lane & 3) * 2;
            #pragma unroll
            for (int half = 0; half < 2; ++half)
                *reinterpret_cast<float2*>(dst + (rl + half * 8) * 128 + cl) =
                    make_float2(acc[mi][ni][half * 2 + 0], acc[mi][ni][half * 2 + 1]);
        }
}

// ===================== int8 engine (projQK) =================================
__device__ __forceinline__ void load_stage_i8(uint32_t sb, int st, int tid,
    const int8_t* __restrict__ A0, const int8_t* __restrict__ A1,
    const int8_t* __restrict__ B0, const int8_t* __restrict__ B1, int k0)
{
    uint32_t base = sb + (uint32_t)st * 12288u;
    #pragma unroll
    for (int it = 0; it < 3; ++it) {
        int c = tid + it * NTHR;          // [0,768)
        if (c < 512) {
            int sl = c >> 8, ch = c & 255;
            int row = ch >> 1, h = ch & 1;
            const int8_t* src = sl ? A1 : A0;
            cpa16(base + (uint32_t)sl * 4096u + swz8(row, h),
                  src + (size_t)row * D_ + k0 + h * 16);
        } else {
            int d = c - 512;
            int sl = d >> 7, ch = d & 127;
            int row = ch >> 1, h = ch & 1;
            const int8_t* src = sl ? B1 : B0;
            cpa16(base + 8192u + (uint32_t)sl * 2048u + swz8(row, h),
                  src + (size_t)row * D_ + k0 + h * 16);
        }
    }
}

__device__ __forceinline__ void compute_stage_i8(uint32_t sb, int st, int lane,
    int wm, int wn, int acc1[4][2][4], int acc2[4][2][4])
{
    uint32_t base = sb + (uint32_t)st * 12288u;
    uint32_t bA0 = base, bA1 = base + 4096u, bB0 = base + 8192u, bB1 = base + 10240u;
    uint32_t b0f[2][2], b1f[2][2];
    {
        uint32_t off = swz8(wn * 16 + (lane & 15), lane >> 4);
        uint32_t r[4];
        ldm_x4(bB0 + off, r);
        b0f[0][0]=r[0]; b0f[0][1]=r[2]; b0f[1][0]=r[1]; b0f[1][1]=r[3];
        ldm_x4(bB1 + off, r);
        b1f[0][0]=r[0]; b1f[0][1]=r[2]; b1f[1][0]=r[1]; b1f[1][1]=r[3];
    }
    const int arow = wm * 64 + (lane & 15);
    const int ah = lane >> 4;
    #pragma unroll
    for (int mi = 0; mi < 4; ++mi) {
        uint32_t off = swz8(arow + mi * 16, ah);
        uint32_t a0[4], a1[4];
        ldm_x4(bA0 + off, a0);
        ldm_x4(bA1 + off, a1);
        #pragma unroll
        for (int ni = 0; ni < 2; ++ni) {
            mma_s8(acc1[mi][ni], a0, b0f[ni]);
            mma_s8(acc2[mi][ni], a0, b1f[ni]);
            mma_s8(acc2[mi][ni], a1, b0f[ni]);
        }
    }
}

// Pack fp32 rows -> int8 2-slice; one warp per row.
__global__ __launch_bounds__(256)
void pack_i8_kernel(const float* __restrict__ x, const float* __restrict__ wq,
                    const float* __restrict__ wk)
{
    const int gw = blockIdx.x * 8 + (threadIdx.x >> 5);
    const int lane = threadIdx.x & 31;
    const float* src; int8_t *d0, *d1; float* sv; int row;
    if (gw < 8192)      { src = x;  d0 = g_xa0;  d1 = g_xa1;  sv = g_sx;  row = gw; }
    else if (gw < 9216) { src = wq; d0 = g_wqa0; d1 = g_wqa1; sv = g_swq; row = gw - 8192; }
    else                { src = wk; d0 = g_wka0; d1 = g_wka1; sv = g_swk; row = gw - 9216; }

    const float4* rp = reinterpret_cast<const float4*>(src + (size_t)row * D_);
    float4 v[8];
    float mx = 1e-30f;
    #pragma unroll
    for (int j = 0; j < 8; ++j) {
        v[j] = rp[lane + j * 32];
        mx = fmaxf(mx, fmaxf(fmaxf(fabsf(v[j].x), fabsf(v[j].y)),
                             fmaxf(fabsf(v[j].z), fabsf(v[j].w))));
    }
    #pragma unroll
    for (int o = 16; o > 0; o >>= 1) mx = fmaxf(mx, __shfl_xor_sync(0xFFFFFFFFu, mx, o));
    const float inv = 127.f / mx;
    if (lane == 0) sv[row] = mx;

    char4* c0p = reinterpret_cast<char4*>(d0) + (size_t)row * 256;
    char4* c1p = reinterpret_cast<char4*>(d1) + (size_t)row * 256;
    #pragma unroll
    for (int j = 0; j < 8; ++j) {
        const float* e = reinterpret_cast<const float*>(&v[j]);
        signed char s0[4], s1[4];
        #pragma unroll
        for (int t = 0; t < 4; ++t) {
            float q = e[t] * inv;
            float a0f = rintf(q);
            int a1 = (int)rintf((q - a0f) * 256.f);
            a1 = a1 > 127 ? 127 : (a1 < -127 ? -127 : a1);
            s0[t] = (signed char)(int)a0f;
            s1[t] = (signed char)a1;
        }
        c0p[lane + j * 32] = make_char4(s0[0], s0[1], s0[2], s0[3]);
        c1p[lane + j * 32] = make_char4(s1[0], s1[1], s1[2], s1[3]);
    }
}

// Q+K projection, int8. CTA tile 128x64. Grid 2048: z=t>>10 (0=Q,1=K),
// by=(t>>4)&63, bx=t&15.
__global__ __launch_bounds__(NTHR, 2)
void tc_projqk_i8()
{
    extern __shared__ char smem[];
    uint32_t sb = smem_u32(smem);
    const int tile = blockIdx.x;
    const int z = tile >> 10, by = (tile >> 4) & 63, bx = tile & 15;

    const int8_t* A0 = g_xa0 + (size_t)by * 128 * D_;
    const int8_t* A1 = g_xa1 + (size_t)by * 128 * D_;
    const int8_t* B0 = (z ? g_wka0 : g_wqa0) + (size_t)bx * 64 * D_;
    const int8_t* B1 = (z ? g_wka1 : g_wqa1) + (size_t)bx * 64 * D_;
    const float*  sw = z ? g_swk : g_swq;

    const int tid = threadIdx.x, lane = tid & 31, wid = tid >> 5;
    const int wm = wid & 1, wn = wid >> 1;

    int acc1[4][2][4], acc2[4][2][4];
    #pragma unroll
    for (int mi = 0; mi < 4; ++mi)
        #pragma unroll
        for (int ni = 0; ni < 2; ++ni)
            #pragma unroll
            for (int j = 0; j < 4; ++j) { acc1[mi][ni][j] = 0; acc2[mi][ni][j] = 0; }

    load_stage_i8(sb, 0, tid, A0, A1, B0, B1, 0);
    asm volatile("cp.async.commit_group;" ::: "memory");
    load_stage_i8(sb, 1, tid, A0, A1, B0, B1, 32);
    asm volatile("cp.async.commit_group;" ::: "memory");
    int st = 0;
    for (int i = 0; i < 32; ++i) {
        if (i + 1 < 32) asm volatile("cp.async.wait_group 1;" ::: "memory");
        else            asm volatile("cp.async.wait_group 0;" ::: "memory");
        __syncthreads();
        if (i + 2 < 32) {
            int slot = st + 2 >= 3 ? st - 1 : st + 2;
            load_stage_i8(sb, slot, tid, A0, A1, B0, B1, (i + 2) * 32);
            asm volatile("cp.async.commit_group;" ::: "memory");
        }
        compute_stage_i8(sb, st, lane, wm, wn, acc1, acc2);
        st = (st == 2) ? 0 : st + 1;
    }

    bf16* Oh = z ? g_kh : g_qh;
    bf16* Ol = z ? g_kl : g_ql;
    const float G = 1.0f / 16129.0f;   // 1/(127*127)
    const float I256 = 1.0f / 256.0f;
    #pragma unroll
    for (int mi = 0; mi < 4; ++mi)
        #pragma unroll
        for (int ni = 0; ni < 2; ++ni) {
            int r0 = by * 128 + wm * 64 + mi * 16 + (lane >> 2);
            int c0 = bx * 64 + wn * 16 + ni * 8 + (lane & 3) * 2;
            float sb0 = sw[c0] * G, sb1 = sw[c0 + 1] * G;
            #pragma unroll
            for (int half = 0; half < 2; ++half) {
                int gr = r0 + half * 8;
                float sa = g_sx[gr];
                float v0 = ((float)acc1[mi][ni][half*2+0] + (float)acc2[mi][ni][half*2+0] * I256) * (sa * sb0);
                float v1 = ((float)acc1[mi][ni][half*2+1] + (float)acc2[mi][ni][half*2+1] * I256) * (sa * sb1);
                bf16 h0 = __float2bfloat16(v0); bf16 l0 = __float2bfloat16(v0 - __bfloat162float(h0));
                bf16 h1 = __float2bfloat16(v1); bf16 l1 = __float2bfloat16(v1 - __bfloat162float(h1));
                *reinterpret_cast<__nv_bfloat162*>(Oh + (size_t)gr * D_ + c0) = __halves2bfloat162(h0, h1);
                *reinterpret_cast<__nv_bfloat162*>(Ol + (size_t)gr * D_ + c0) = __halves2bfloat162(l0, l1);
            }
        }
}

// ===================== remaining pipeline (from R12) ========================
// Split X and Wv only (Q/K weights go through the int8 pack instead).
__global__ __launch_bounds__(256)
void split_xv_kernel(const float4* __restrict__ x, const float4* __restrict__ wv,
                     __nv_bfloat162* __restrict__ xh,  __nv_bfloat162* __restrict__ xl,
                     __nv_bfloat162* __restrict__ wvh, __nv_bfloat162* __restrict__ wvl)
{
    const int t = blockIdx.y;
    const float4* in; __nv_bfloat162 *hi, *lo; int n4;
    if (t == 0) { in = x;  hi = xh;  lo = xl;  n4 = M_*D_/4; }
    else        { in = wv; hi = wvh; lo = wvl; n4 = D_*D_/4; }
    int i = blockIdx.x * 256 + threadIdx.x;
    if (i >= n4) return;
    float4 v = in[i];
    bf16 h0 = __float2bfloat16(v.x); bf16 l0 = __float2bfloat16(v.x - __bfloat162float(h0));
    bf16 h1 = __float2bfloat16(v.y); bf16 l1 = __float2bfloat16(v.y - __bfloat162float(h1));
    bf16 h2 = __float2bfloat16(v.z); bf16 l2 = __float2bfloat16(v.z - __bfloat162float(h2));
    bf16 h3 = __float2bfloat16(v.w); bf16 l3 = __float2bfloat16(v.w - __bfloat162float(h3));
    hi[2*i]   = __halves2bfloat162(h0, h1);
    hi[2*i+1] = __halves2bfloat162(h2, h3);
    lo[2*i]   = __halves2bfloat162(l0, l1);
    lo[2*i+1] = __halves2bfloat162(l2, l3);
}

// Merged scores + V-projection (R12 layout: 544 scores + 368 V fulls + 288 halves)
__global__ __launch_bounds__(NTHR, 2)
void tc_sv_kernel()
{
    extern __shared__ char smem[];
    uint32_t sb = smem_u32(smem);
    const int id = blockIdx.x;

    if (id < 544) {
        const int b = id / 136;
        const int idx = id % 136;
        int by = (int)((sqrtf(8.f * idx + 1.f) - 1.f) * 0.5f);
        while ((by + 1) * (by + 2) / 2 <= idx) ++by;
        while (by * (by + 1) / 2 > idx) --by;
        const int bx = idx - by * (by + 1) / 2;

        size_t aoff = ((size_t)b * S_ + by * 128) * D_;
        size_t boff = ((size_t)b * S_ + bx * 128) * D_;
        float acc[4][4][4];
        gemm_run<0>(sb, g_qh + aoff, g_ql + aoff, D_,
                        g_kh + boff, g_kl + boff, D_, D_ / 32, acc);

        const int tid = threadIdx.x, lane = tid & 31, wid = tid >> 5;
        const int wm = wid & 1, wn = wid >> 1;
        const bool diag = (bx == by);
        const float alpha = 0.03125f;
        float* out = g_s + (size_t)b * S_ * S_;
        #pragma unroll
        for (int mi = 0; mi < 4; ++mi)
            #pragma unroll
            for (int ni = 0; ni < 4; ++ni) {
                int r0 = by * 128 + wm * 64 + mi * 16 + (lane >> 2);
                int c0 = bx * 128 + wn * 32 + ni * 8 + (lane & 3) * 2;
                #pragma unroll
                for (int half = 0; half < 2; ++half) {
                    int gr = r0 + half * 8;
                    float s0 = acc[mi][ni][half * 2 + 0] * alpha;
                    float s1 = acc[mi][ni][half * 2 + 1] * alpha;
                    if (diag) {
                        if (c0 > gr)     s0 = -CUDART_INF_F;
                        if (c0 + 1 > gr) s1 = -CUDART_INF_F;
                    }
                    *reinterpret_cast<float2*>(out + (size_t)gr * S_ + c0) = make_float2(s0, s1);
                }
            }
    } else {
        int vt, niter, k0e, piece;
        if (id < 912) { vt = id - 544; niter = 32; k0e = 0; piece = -1; }
        else { int p = id - 912; vt = 368 + (p >> 1); niter = 16; k0e = (p & 1) * 512; piece = p; }
        const int by = vt >> 3, bx = vt & 7;

        float acc[4][4][4];
        gemm_run<0>(sb,
            g_xh + (size_t)by * 128 * D_ + k0e, g_xl + (size_t)by * 128 * D_ + k0e, D_,
            g_wvh + (size_t)bx * 128 * D_ + k0e, g_wvl + (size_t)bx * 128 * D_ + k0e, D_,
            niter, acc);

        if (piece < 0) epi_bf16_split(acc, by, bx, g_vh, g_vl);
        else epi_f32_tile(acc, reinterpret_cast<float*>(g_ph) + (size_t)piece * 16384);
    }
}

__global__ __launch_bounds__(256)
void v_combine_kernel()
{
    const int t = blockIdx.x;              // [0,144)
    const int vt = 368 + t;
    const int by = vt >> 3, bx = vt & 7;
    const float* scr = reinterpret_cast<const float*>(g_ph);
    const float4* p0 = reinterpret_cast<const float4*>(scr + (size_t)(2*t)   * 16384);
    const float4* p1 = reinterpret_cast<const float4*>(scr + (size_t)(2*t+1) * 16384);
    const int tid = threadIdx.x;
    #pragma unroll
    for (int j = 0; j < 16; ++j) {
        int f4 = j * 256 + tid;
        int r  = f4 >> 5;
        int c4 = f4 & 31;
        float4 a = p0[f4], b = p1[f4];
        float v[4] = {a.x + b.x, a.y + b.y, a.z + b.z, a.w + b.w};
        size_t base = (size_t)(by * 128 + r) * D_ + bx * 128 + c4 * 4;
        #pragma unroll
        for (int e = 0; e < 4; e += 2) {
            bf16 h0 = __float2bfloat16(v[e]);   bf16 l0 = __float2bfloat16(v[e]   - __bfloat162float(h0));
            bf16 h1 = __float2bfloat16(v[e+1]); bf16 l1 = __float2bfloat16(v[e+1] - __bfloat162float(h1));
            *reinterpret_cast<__nv_bfloat162*>(g_vh + base + e) = __halves2bfloat162(h0, h1);
            *reinterpret_cast<__nv_bfloat162*>(g_vl + base + e) = __halves2bfloat162(l0, l1);
        }
    }
}

__global__ __launch_bounds__(256)
void softmax_split_kernel()
{
    const int q = blockIdx.x;
    const int b = blockIdx.y;
    const size_t off = (size_t)b * S_ * S_ + (size_t)q * S_;
    const float2* row2 = reinterpret_cast<const float2*>(g_s + off);
    const int L2 = (((q >> 7) + 1) << 7) >> 1;
    const int tid = threadIdx.x;

    float2 v[4];
    float m = -CUDART_INF_F;
    #pragma unroll
    for (int j = 0; j < 4; ++j) {
        int i = tid + j * 256;
        if (i < L2) { v[j] = row2[i]; m = fmaxf(m, fmaxf(v[j].x, v[j].y)); }
        else        { v[j] = make_float2(-CUDART_INF_F, -CUDART_INF_F); }
    }
    #pragma unroll
    for (int o = 16; o > 0; o >>= 1) m = fmaxf(m, __shfl_xor_sync(0xFFFFFFFFu, m, o));
    __shared__ float red[8];
    if ((tid & 31) == 0) red[tid >> 5] = m;
    __syncthreads();
    float mg = red[0];
    #pragma unroll
    for (int j = 1; j < 8; ++j) mg = fmaxf(mg, red[j]);
    __syncthreads();

    float sum = 0.f;
    #pragma unroll
    for (int j = 0; j < 4; ++j) {
        int i = tid + j * 256;
        if (i < L2) {
            v[j].x = __expf(v[j].x - mg);
            v[j].y = __expf(v[j].y - mg);
            sum += v[j].x + v[j].y;
        }
    }
    #pragma unroll
    for (int o = 16; o > 0; o >>= 1) sum += __shfl_xor_sync(0xFFFFFFFFu, sum, o);
    if ((tid & 31) == 0) red[tid >> 5] = sum;
    __syncthreads();
    float tot = 0.f;
    #pragma unroll
    for (int j = 0; j < 8; ++j) tot += red[j];
    float inv = 1.0f / tot;

    __nv_bfloat162* ph2 = reinterpret_cast<__nv_bfloat162*>(g_ph + off);
    __nv_bfloat162* pl2 = reinterpret_cast<__nv_bfloat162*>(g_pl + off);
    #pragma unroll
    for (int j = 0; j < 4; ++j) {
        int i = tid + j * 256;
        if (i < L2) {
            float p0 = v[j].x * inv, p1 = v[j].y * inv;
            bf16 h0 = __float2bfloat16(p0); bf16 l0 = __float2bfloat16(p0 - __bfloat162float(h0));
            bf16 h1 = __float2bfloat16(p1); bf16 l1 = __float2bfloat16(p1 - __bfloat162float(h1));
            ph2[i] = __halves2bfloat162(h0, h1);
            pl2[i] = __halves2bfloat162(l0, l1);
        }
    }
}

__global__ __launch_bounds__(NTHR, 2)
void tc_pv_kernel(float* __restrict__ out)
{
    const int bx = blockIdx.x;
    const int b  = blockIdx.y;
    const int o  = blockIdx.z;
    const int by = d_pv_by[o];
    const int piece = d_pv_piece[o];

    extern __shared__ char smem[];
    uint32_t sb = smem_u32(smem);

    const int total = (by + 1) * 4;
    int niter, k0i;
    if (piece < 0) { niter = total;      k0i = 0; }
    else           { niter = total >> 1; k0i = piece ? niter : 0; }
    const int k0 = k0i * 32;

    size_t aoff = (size_t)b * S_ * S_ + (size_t)by * 128 * S_ + k0;
    size_t boff = (size_t)b * S_ * D_ + (size_t)bx * 128 + (size_t)k0 * D_;

    float acc[4][4][4];
    gemm_run<1>(sb, g_ph + aoff, g_pl + aoff, S_,
                    g_vh + boff, g_vl + boff, D_, niter, acc);

    const int tid = threadIdx.x, lane = tid & 31, wid = tid >> 5;
    const int wm = wid & 1, wn = wid >> 1;

    if (piece == 0) {
        const int sidx = (by - 8) + 8 * (bx + 8 * b);
        epi_f32_tile(acc, g_s + (size_t)sidx * 16384);
    } else {
        #pragma unroll
        for (int mi = 0; mi < 4; ++mi)
            #pragma unroll
            for (int ni = 0; ni < 4; ++ni) {
                int r0 = by * 128 + wm * 64 + mi * 16 + (lane >> 2);
                int c0 = bx * 128 + wn * 32 + ni * 8 + (lane & 3) * 2;
                #pragma unroll
                for (int half = 0; half < 2; ++half) {
                    int gq = r0 + half * 8;
                    *reinterpret_cast<float2*>(out + ((size_t)(b * S_ + gq)) * D_ + c0) =
                        make_float2(acc[mi][ni][half * 2 + 0], acc[mi][ni][half * 2 + 1]);
                }
            }
    }
}

__global__ __launch_bounds__(256)
void pv_combine_kernel(float* __restrict__ out)
{
    const int tile = blockIdx.x;
    const int b  = tile >> 6;
    const int bx = (tile >> 3) & 7;
    const int by = (tile & 7) + 8;
    const float4* src = reinterpret_cast<const float4*>(g_s + (size_t)tile * 16384);
    const int tid = threadIdx.x;
    #pragma unroll
    for (int j = 0; j < 16; ++j) {
        int f4 = j * 256 + tid;
        int r  = f4 >> 5;
        int c4 = f4 & 31;
        float4 s = src[f4];
        float4* op = reinterpret_cast<float4*>(
            out + ((size_t)(b * S_ + by * 128 + r)) * D_ + bx * 128 + c4 * 4);
        float4 v = *op;
        v.x += s.x; v.y += s.y; v.z += s.z; v.w += s.w;
        *op = v;
    }
}

// ---------------------------------------------------------------------------
extern "C" void kernel_launch(void* const* d_in, const int* in_sizes, int n_in,
                              void* d_out, int out_size)
{
    const float* x  = (const float*)d_in[0];
    const float* wq = (const float*)d_in[1];
    const float* wk = (const float*)d_in[2];
    const float* wv = (const float*)d_in[3];
    float* out = (float*)d_out;

    bf16 *xh, *xl, *wvh, *wvl;
    cudaGetSymbolAddress((void**)&xh,  g_xh);  cudaGetSymbolAddress((void**)&xl,  g_xl);
    cudaGetSymbolAddress((void**)&wvh, g_wvh); cudaGetSymbolAddress((void**)&wvl, g_wvl);

    static bool attr_done = false;
    if (!attr_done) {
        cudaFuncSetAttribute(tc_projqk_i8, cudaFuncAttributeMaxDynamicSharedMemorySize, SMEM_I8);
        cudaFuncSetAttribute(tc_sv_kernel, cudaFuncAttributeMaxDynamicSharedMemorySize, SMEM_TOTAL);
        cudaFuncSetAttribute(tc_pv_kernel, cudaFuncAttributeMaxDynamicSharedMemorySize, SMEM_TOTAL);
        attr_done = true;
    }

    // Pack X/Wq/Wk to int8 slices; split X/Wv to bf16 hi/lo
    pack_i8_kernel<<<1280, 256>>>(x, wq, wk);
    {
        dim3 gs((M_ * D_ / 4 + 255) / 256, 2);
        split_xv_kernel<<<gs, 256>>>((const float4*)x, (const float4*)wv,
            (__nv_bfloat162*)xh, (__nv_bfloat162*)xl,
            (__nv_bfloat162*)wvh, (__nv_bfloat162*)wvl);
    }

    // Q+K projections on int8 tensor path (2048 light tiles)
    tc_projqk_i8<<<2048, NTHR, SMEM_I8>>>();

    // Merged scores + V projection, then V tail combine
    tc_sv_kernel<<<1200, NTHR, SMEM_TOTAL>>>();
    v_combine_kernel<<<144, 256>>>();

    // Softmax + P split
    dim3 gsm(S_, B_);
    softmax_split_kernel<<<gsm, 256>>>();

    // P @ V with split-K, then combine
    dim3 gpv(D_ / 128, B_, 24);
    tc_pv_kernel<<<gpv, NTHR, SMEM_TOTAL>>>(out);
    pv_combine_kernel<<<256, 256>>>(out);
}

// round 16
// speedup vs baseline: 1.7474x; 1.7474x over previous
#include <cuda_runtime.h>
#include <cuda_bf16.h>
#include <cstdint>
#include <math.h>
#include <math_constants.h>

#define B_ 4
#define S_ 2048
#define D_ 1024
#define M_ (B_*S_)   // 8192

typedef __nv_bfloat16 bf16;

// ---------------------------------------------------------------------------
// Scratch (__device__ globals; allocation-free)
// ---------------------------------------------------------------------------
__device__ __align__(256) bf16 g_xh[M_*D_], g_xl[M_*D_];
__device__ __align__(256) bf16 g_wqh[D_*D_], g_wql[D_*D_];
__device__ __align__(256) bf16 g_wkh[D_*D_], g_wkl[D_*D_];
__device__ __align__(256) bf16 g_wvh[D_*D_], g_wvl[D_*D_];
__device__ __align__(256) bf16 g_qh[M_*D_], g_ql[M_*D_];
__device__ __align__(256) bf16 g_kh[M_*D_], g_kl[M_*D_];
__device__ __align__(256) bf16 g_vh[M_*D_], g_vl[M_*D_];      // V natural [b][s][d]
__device__ __align__(256) float g_s[(size_t)B_*S_*S_];        // scores; then PV split-K partials
__device__ __align__(256) bf16 g_ph[(size_t)B_*S_*S_], g_pl[(size_t)B_*S_*S_];
// Proj split-K fp32 partials live in g_ph (dead until softmax writes it).

// PV schedule: 24 entries per (b,bx), descending niter for work-steal packing.
__device__ const int d_pv_by[24]    = {15,15,7,14,14,13,13,6,12,12,11,11,5,10,10,9,9,4,8,8,3,2,1,0};
__device__ const int d_pv_piece[24] = { 0, 1,-1, 0, 1, 0, 1,-1, 0, 1, 0, 1,-1, 0, 1,0,1,-1,0,1,-1,-1,-1,-1};

// ---------------------------------------------------------------------------
#define LDBT_S 136
#define STG 33792u
#define OFF_AH(s) ((s)*STG)
#define OFF_AL(s) ((s)*STG + 8192u)
#define OFF_BH(s) ((s)*STG + 16384u)
#define OFF_BL(s) ((s)*STG + 25088u)
#define SMEM_TOTAL (3*33792)
#define NTHR 256

__device__ __forceinline__ uint32_t swz(int r, int k) {
    return (uint32_t)(r * 64 + ((((k >> 3) ^ ((r >> 1) & 3)) << 4) | ((k & 7) << 1)));
}
__device__ __forceinline__ uint32_t smem_u32(const void* p) {
    uint32_t a;
    asm("{ .reg .u64 t; cvta.to.shared.u64 t, %1; cvt.u32.u64 %0, t; }" : "=r"(a) : "l"(p));
    return a;
}
__device__ __forceinline__ void cpa16(uint32_t s, const void* g) {
    asm volatile("cp.async.cg.shared.global [%0], [%1], 16;" :: "r"(s), "l"(g));
}
__device__ __forceinline__ void ldm_x4(uint32_t addr, uint32_t r[4]) {
    asm volatile("ldmatrix.sync.aligned.m8n8.x4.shared.b16 {%0,%1,%2,%3}, [%4];"
        : "=r"(r[0]), "=r"(r[1]), "=r"(r[2]), "=r"(r[3]) : "r"(addr));
}
__device__ __forceinline__ void ldm_x4_t(uint32_t addr, uint32_t r[4]) {
    asm volatile("ldmatrix.sync.aligned.m8n8.x4.trans.shared.b16 {%0,%1,%2,%3}, [%4];"
        : "=r"(r[0]), "=r"(r[1]), "=r"(r[2]), "=r"(r[3]) : "r"(addr));
}
__device__ __forceinline__ void mma16816(float c[4], const uint32_t a[4], const uint32_t b[2]) {
    asm volatile("mma.sync.aligned.m16n8k16.row.col.f32.bf16.bf16.f32 "
        "{%0,%1,%2,%3}, {%4,%5,%6,%7}, {%8,%9}, {%0,%1,%2,%3};"
        : "+f"(c[0]), "+f"(c[1]), "+f"(c[2]), "+f"(c[3])
        : "r"(a[0]), "r"(a[1]), "r"(a[2]), "r"(a[3]), "r"(b[0]), "r"(b[1]));
}

// ---------------------------------------------------------------------------
template<int BT>
__device__ __forceinline__ void load_stage(uint32_t sb, int st, int tid,
    const bf16* __restrict__ Ah, const bf16* __restrict__ Al, int lda,
    const bf16* __restrict__ Bh, const bf16* __restrict__ Bl, int ldb, int k0)
{
    #pragma unroll
    for (int it = 0; it < 2; ++it) {
        int c = tid + it * NTHR;
        int row = c >> 2;
        int kc  = (c & 3) << 3;
        uint32_t so = swz(row, kc);
        cpa16(sb + OFF_AH(st) + so, Ah + (size_t)row * lda + k0 + kc);
        cpa16(sb + OFF_AL(st) + so, Al + (size_t)row * lda + k0 + kc);
        if (BT == 0) {
            cpa16(sb + OFF_BH(st) + so, Bh + (size_t)row * ldb + k0 + kc);
            cpa16(sb + OFF_BL(st) + so, Bl + (size_t)row * ldb + k0 + kc);
        } else {
            int br = c >> 4;
            int bn = (c & 15) << 3;
            uint32_t bo = (uint32_t)((br * LDBT_S + bn) * 2);
            cpa16(sb + OFF_BH(st) + bo, Bh + (size_t)(k0 + br) * ldb + bn);
            cpa16(sb + OFF_BL(st) + bo, Bl + (size_t)(k0 + br) * ldb + bn);
        }
    }
}

template<int BT>
__device__ __forceinline__ void compute_stage(uint32_t sb, int st, int lane,
                                              int wm, int wn, float acc[4][4][4])
{
    const uint32_t sAh = sb + OFF_AH(st), sAl = sb + OFF_AL(st);
    const uint32_t sBh = sb + OFF_BH(st), sBl = sb + OFF_BL(st);

    #pragma unroll
    for (int ks = 0; ks < 2; ++ks) {
        uint32_t bh[4][2], bl[4][2];
        if (BT == 0) {
            int nr = (lane & 7) + ((lane >> 4) & 1) * 8;
            int kh = ks * 16 + ((lane >> 3) & 1) * 8;
            #pragma unroll
            for (int np = 0; np < 2; ++np) {
                uint32_t off = swz(wn * 32 + np * 16 + nr, kh);
                uint32_t r[4];
                ldm_x4(sBh + off, r);
                bh[2*np][0]=r[0]; bh[2*np][1]=r[1]; bh[2*np+1][0]=r[2]; bh[2*np+1][1]=r[3];
                ldm_x4(sBl + off, r);
                bl[2*np][0]=r[0]; bl[2*np][1]=r[1]; bl[2*np+1][0]=r[2]; bl[2*np+1][1]=r[3];
            }
        } else {
            int kr = ks * 16 + ((lane >> 3) & 1) * 8 + (lane & 7);
            int nh = ((lane >> 4) & 1) * 8;
            #pragma unroll
            for (int np = 0; np < 2; ++np) {
                uint32_t off = (uint32_t)((kr * LDBT_S + wn * 32 + np * 16 + nh) * 2);
                uint32_t r[4];
                ldm_x4_t(sBh + off, r);
                bh[2*np][0]=r[0]; bh[2*np][1]=r[1]; bh[2*np+1][0]=r[2]; bh[2*np+1][1]=r[3];
                ldm_x4_t(sBl + off, r);
                bl[2*np][0]=r[0]; bl[2*np][1]=r[1]; bl[2*np+1][0]=r[2]; bl[2*np+1][1]=r[3];
            }
        }

        const int arow = wm * 64 + (lane & 15);
        const int akh  = ks * 16 + (lane >> 4) * 8;
        #pragma unroll
        for (int mi = 0; mi < 4; ++mi) {
            uint32_t ah[4], al[4];
            uint32_t off = swz(arow + mi * 16, akh);
            ldm_x4(sAh + off, ah);
            ldm_x4(sAl + off, al);
            #pragma unroll
            for (int ni = 0; ni < 4; ++ni) {
                mma16816(acc[mi][ni], ah, bh[ni]);
                mma16816(acc[mi][ni], ah, bl[ni]);
                mma16816(acc[mi][ni], al, bh[ni]);
            }
        }
    }
}

// 3-stage pipelined mainloop; one __syncthreads per iteration. niter >= 2.
template<int BT>
__device__ __forceinline__ void gemm_run(uint32_t sb,
    const bf16* __restrict__ Ah, const bf16* __restrict__ Al, int lda,
    const bf16* __restrict__ Bh, const bf16* __restrict__ Bl, int ldb,
    int niter, float acc[4][4][4])
{
    const int tid = threadIdx.x, lane = tid & 31, wid = tid >> 5;
    const int wm = wid & 1, wn = wid >> 1;

    #pragma unroll
    for (int mi = 0; mi < 4; ++mi)
        #pragma unroll
        for (int ni = 0; ni < 4; ++ni)
            #pragma unroll
            for (int j = 0; j < 4; ++j) acc[mi][ni][j] = 0.f;

    load_stage<BT>(sb, 0, tid, Ah, Al, lda, Bh, Bl, ldb, 0);
    asm volatile("cp.async.commit_group;" ::: "memory");
    load_stage<BT>(sb, 1, tid, Ah, Al, lda, Bh, Bl, ldb, 32);
    asm volatile("cp.async.commit_group;" ::: "memory");

    int st = 0;
    for (int i = 0; i < niter; ++i) {
        if (i + 1 < niter) asm volatile("cp.async.wait_group 1;" ::: "memory");
        else               asm volatile("cp.async.wait_group 0;" ::: "memory");
        __syncthreads();
        if (i + 2 < niter) {
            int slot = st + 2 >= 3 ? st - 1 : st + 2;
            load_stage<BT>(sb, slot, tid, Ah, Al, lda, Bh, Bl, ldb, (i + 2) * 32);
            asm volatile("cp.async.commit_group;" ::: "memory");
        }
        compute_stage<BT>(sb, st, lane, wm, wn, acc);
        st = (st == 2) ? 0 : st + 1;
    }
}

// Shared epilogue helpers ----------------------------------------------------
__device__ __forceinline__ void epi_bf16_split(float acc[4][4][4], int by, int bx,
                                               bf16* Oh, bf16* Ol)
{
    const int tid = threadIdx.x, lane = tid & 31, wid = tid >> 5;
    const int wm = wid & 1, wn = wid >> 1;
    #pragma unroll
    for (int mi = 0; mi < 4; ++mi)
        #pragma unroll
        for (int ni = 0; ni < 4; ++ni) {
            int r0 = by * 128 + wm * 64 + mi * 16 + (lane >> 2);
            int c0 = bx * 128 + wn * 32 + ni * 8 + (lane & 3) * 2;
            #pragma unroll
            for (int half = 0; half < 2; ++half) {
                int gr = r0 + half * 8;
                float v0 = acc[mi][ni][half * 2 + 0];
                float v1 = acc[mi][ni][half * 2 + 1];
                bf16 h0 = __float2bfloat16(v0); bf16 l0 = __float2bfloat16(v0 - __bfloat162float(h0));
                bf16 h1 = __float2bfloat16(v1); bf16 l1 = __float2bfloat16(v1 - __bfloat162float(h1));
                *reinterpret_cast<__nv_bfloat162*>(Oh + (size_t)gr * D_ + c0) = __halves2bfloat162(h0, h1);
                *reinterpret_cast<__nv_bfloat162*>(Ol + (size_t)gr * D_ + c0) = __halves2bfloat162(l0, l1);
            }
        }
}

__device__ __forceinline__ void epi_f32_tile(float acc[4][4][4], float* dst)
{
    const int tid = threadIdx.x, lane = tid & 31, wid = tid >> 5;
    const int wm = wid & 1, wn = wid >> 1;
    #pragma unroll
    for (int mi = 0; mi < 4; ++mi)
        #pragma unroll
        for (int ni = 0; ni < 4; ++ni) {
            int rl = wm * 64 + mi * 16 + (lane >> 2);
            int cl = wn * 32 + ni * 8 + (lane & 3) * 2;
            #pragma unroll
            for (int half = 0; half < 2; ++half)
                *reinterpret_cast<float2*>(dst + (rl + half * 8) * 128 + cl) =
                    make_float2(acc[mi][ni][half * 2 + 0], acc[mi][ni][half * 2 + 1]);
        }
}

// ---------------------------------------------------------------------------
// fp32 -> bf16 hi/lo splits. Tight grids: one launch for X, one for the 3 Ws.
// ---------------------------------------------------------------------------
__device__ __forceinline__ void split4(const float4 v, __nv_bfloat162* hi,
                                       __nv_bfloat162* lo, int i)
{
    bf16 h0 = __float2bfloat16(v.x); bf16 l0 = __float2bfloat16(v.x - __bfloat162float(h0));
    bf16 h1 = __float2bfloat16(v.y); bf16 l1 = __float2bfloat16(v.y - __bfloat162float(h1));
    bf16 h2 = __float2bfloat16(v.z); bf16 l2 = __float2bfloat16(v.z - __bfloat162float(h2));
    bf16 h3 = __float2bfloat16(v.w); bf16 l3 = __float2bfloat16(v.w - __bfloat162float(h3));
    hi[2*i]   = __halves2bfloat162(h0, h1);
    hi[2*i+1] = __halves2bfloat162(h2, h3);
    lo[2*i]   = __halves2bfloat162(l0, l1);
    lo[2*i+1] = __halves2bfloat162(l2, l3);
}

__global__ __launch_bounds__(256)
void split_x_kernel(const float4* __restrict__ x,
                    __nv_bfloat162* __restrict__ xh, __nv_bfloat162* __restrict__ xl)
{
    int i = blockIdx.x * 256 + threadIdx.x;   // < M_*D_/4 exactly
    split4(x[i], xh, xl, i);
}

__global__ __launch_bounds__(256)
void split_w_kernel(const float4* __restrict__ wq, const float4* __restrict__ wk,
                    const float4* __restrict__ wv,
                    __nv_bfloat162* __restrict__ wqh, __nv_bfloat162* __restrict__ wql,
                    __nv_bfloat162* __restrict__ wkh, __nv_bfloat162* __restrict__ wkl,
                    __nv_bfloat162* __restrict__ wvh, __nv_bfloat162* __restrict__ wvl)
{
    const int t = blockIdx.y;
    const float4* in; __nv_bfloat162 *hi, *lo;
    if (t == 0)      { in = wq; hi = wqh; lo = wql; }
    else if (t == 1) { in = wk; hi = wkh; lo = wkl; }
    else             { in = wv; hi = wvh; lo = wvl; }
    int i = blockIdx.x * 256 + threadIdx.x;   // < D_*D_/4 exactly
    split4(in[i], hi, lo, i);
}

// ---------------------------------------------------------------------------
// Q+K projection. Grid 1136: id<912 full tile (Q tiles 0..511, K tiles 0..399);
// id>=912: 224 k-half pieces of K tiles 400..511 -> fp32 partials in g_ph.
// ---------------------------------------------------------------------------
__global__ __launch_bounds__(NTHR, 2)
void tc_projqk_kernel(const bf16* __restrict__ Ah, const bf16* __restrict__ Al)
{
    extern __shared__ char smem[];
    uint32_t sb = smem_u32(smem);
    const int id = blockIdx.x;

    int tile, niter, k0e, piece;
    if (id < 912) { tile = id; niter = 32; k0e = 0; piece = -1; }
    else { int p = id - 912; tile = 912 + (p >> 1); niter = 16; k0e = (p & 1) * 512; piece = p; }
    const int z = tile >> 9, by = (tile >> 3) & 63, bx = tile & 7;

    const bf16 *Bh = (z == 0) ? g_wqh : g_wkh;
    const bf16 *Bl = (z == 0) ? g_wql : g_wkl;

    float acc[4][4][4];
    gemm_run<0>(sb,
        Ah + (size_t)by * 128 * D_ + k0e, Al + (size_t)by * 128 * D_ + k0e, D_,
        Bh + (size_t)bx * 128 * D_ + k0e, Bl + (size_t)bx * 128 * D_ + k0e, D_,
        niter, acc);

    if (piece < 0) {
        epi_bf16_split(acc, by, bx, (z == 0) ? g_qh : g_kh, (z == 0) ? g_ql : g_kl);
    } else {
        epi_f32_tile(acc, reinterpret_cast<float*>(g_ph) + (size_t)piece * 16384);
    }
}

// Combine 224 K half-partials into K hi/lo (tiles 912..1023, all z=1).
__global__ __launch_bounds__(256)
void qk_combine_kernel()
{
    const int t = blockIdx.x;              // [0,112)
    const int tile = 912 + t;
    const int by = (tile >> 3) & 63, bx = tile & 7;
    const float* scr = reinterpret_cast<const float*>(g_ph);
    const float4* p0 = reinterpret_cast<const float4*>(scr + (size_t)(2*t)   * 16384);
    const float4* p1 = reinterpret_cast<const float4*>(scr + (size_t)(2*t+1) * 16384);
    const int tid = threadIdx.x;

    #pragma unroll
    for (int j = 0; j < 16; ++j) {
        int f4 = j * 256 + tid;            // [0,4096)
        int r  = f4 >> 5;
        int c4 = f4 & 31;
        float4 a = p0[f4], b = p1[f4];
        float v[4] = {a.x + b.x, a.y + b.y, a.z + b.z, a.w + b.w};
        size_t base = (size_t)(by * 128 + r) * D_ + bx * 128 + c4 * 4;
        #pragma unroll
        for (int e = 0; e < 4; e += 2) {
            bf16 h0 = __float2bfloat16(v[e]);   bf16 l0 = __float2bfloat16(v[e]   - __bfloat162float(h0));
            bf16 h1 = __float2bfloat16(v[e+1]); bf16 l1 = __float2bfloat16(v[e+1] - __bfloat162float(h1));
            *reinterpret_cast<__nv_bfloat162*>(g_kh + base + e) = __halves2bfloat162(h0, h1);
            *reinterpret_cast<__nv_bfloat162*>(g_kl + base + e) = __halves2bfloat162(l0, l1);
        }
    }
}

// ---------------------------------------------------------------------------
// Merged scores + V-projection. Grid 1200:
//   id <  544: scores tile (b = id/136, triangular idx = id%136) -> g_s
//   id <  912: V-proj full tile vt = id-544 (vt 0..367)          -> g_vh/g_vl
//   id < 1200: V-proj half piece p = id-912 of vt = 368+(p>>1)   -> g_ph scratch
// ---------------------------------------------------------------------------
__global__ __launch_bounds__(NTHR, 2)
void tc_sv_kernel()
{
    extern __shared__ char smem[];
    uint32_t sb = smem_u32(smem);
    const int id = blockIdx.x;

    if (id < 544) {
        const int b = id / 136;
        const int idx = id % 136;
        int by = (int)((sqrtf(8.f * idx + 1.f) - 1.f) * 0.5f);
        while ((by + 1) * (by + 2) / 2 <= idx) ++by;
        while (by * (by + 1) / 2 > idx) --by;
        const int bx = idx - by * (by + 1) / 2;

        size_t aoff = ((size_t)b * S_ + by * 128) * D_;
        size_t boff = ((size_t)b * S_ + bx * 128) * D_;
        float acc[4][4][4];
        gemm_run<0>(sb, g_qh + aoff, g_ql + aoff, D_,
                        g_kh + boff, g_kl + boff, D_, D_ / 32, acc);

        const int tid = threadIdx.x, lane = tid & 31, wid = tid >> 5;
        const int wm = wid & 1, wn = wid >> 1;
        const bool diag = (bx == by);
        const float alpha = 0.03125f;
        float* out = g_s + (size_t)b * S_ * S_;
        #pragma unroll
        for (int mi = 0; mi < 4; ++mi)
            #pragma unroll
            for (int ni = 0; ni < 4; ++ni) {
                int r0 = by * 128 + wm * 64 + mi * 16 + (lane >> 2);
                int c0 = bx * 128 + wn * 32 + ni * 8 + (lane & 3) * 2;
                #pragma unroll
                for (int half = 0; half < 2; ++half) {
                    int gr = r0 + half * 8;
                    float s0 = acc[mi][ni][half * 2 + 0] * alpha;
                    float s1 = acc[mi][ni][half * 2 + 1] * alpha;
                    if (diag) {
                        if (c0 > gr)     s0 = -CUDART_INF_F;
                        if (c0 + 1 > gr) s1 = -CUDART_INF_F;
                    }
                    *reinterpret_cast<float2*>(out + (size_t)gr * S_ + c0) = make_float2(s0, s1);
                }
            }
    } else {
        int vt, niter, k0e, piece;
        if (id < 912) { vt = id - 544; niter = 32; k0e = 0; piece = -1; }
        else { int p = id - 912; vt = 368 + (p >> 1); niter = 16; k0e = (p & 1) * 512; piece = p; }
        const int by = vt >> 3, bx = vt & 7;

        float acc[4][4][4];
        gemm_run<0>(sb,
            g_xh + (size_t)by * 128 * D_ + k0e, g_xl + (size_t)by * 128 * D_ + k0e, D_,
            g_wvh + (size_t)bx * 128 * D_ + k0e, g_wvl + (size_t)bx * 128 * D_ + k0e, D_,
            niter, acc);

        if (piece < 0) epi_bf16_split(acc, by, bx, g_vh, g_vl);
        else epi_f32_tile(acc, reinterpret_cast<float*>(g_ph) + (size_t)piece * 16384);
    }
}

// Combine 288 V half-partials into V hi/lo (v-tiles 368..511).
__global__ __launch_bounds__(256)
void v_combine_kernel()
{
    const int t = blockIdx.x;              // [0,144)
    const int vt = 368 + t;
    const int by = vt >> 3, bx = vt & 7;
    const float* scr = reinterpret_cast<const float*>(g_ph);
    const float4* p0 = reinterpret_cast<const float4*>(scr + (size_t)(2*t)   * 16384);
    const float4* p1 = reinterpret_cast<const float4*>(scr + (size_t)(2*t+1) * 16384);
    const int tid = threadIdx.x;
    #pragma unroll
    for (int j = 0; j < 16; ++j) {
        int f4 = j * 256 + tid;
        int r  = f4 >> 5;
        int c4 = f4 & 31;
        float4 a = p0[f4], b = p1[f4];
        float v[4] = {a.x + b.x, a.y + b.y, a.z + b.z, a.w + b.w};
        size_t base = (size_t)(by * 128 + r) * D_ + bx * 128 + c4 * 4;
        #pragma unroll
        for (int e = 0; e < 4; e += 2) {
            bf16 h0 = __float2bfloat16(v[e]);   bf16 l0 = __float2bfloat16(v[e]   - __bfloat162float(h0));
            bf16 h1 = __float2bfloat16(v[e+1]); bf16 l1 = __float2bfloat16(v[e+1] - __bfloat162float(h1));
            *reinterpret_cast<__nv_bfloat162*>(g_vh + base + e) = __halves2bfloat162(h0, h1);
            *reinterpret_cast<__nv_bfloat162*>(g_vl + base + e) = __halves2bfloat162(l0, l1);
        }
    }
}

// ---------------------------------------------------------------------------
// Softmax over causal prefix; float2 in, bf16x2 h/l out.
// ---------------------------------------------------------------------------
__global__ __launch_bounds__(256)
void softmax_split_kernel()
{
    const int q = blockIdx.x;
    const int b = blockIdx.y;
    const size_t off = (size_t)b * S_ * S_ + (size_t)q * S_;
    const float2* row2 = reinterpret_cast<const float2*>(g_s + off);
    const int L2 = (((q >> 7) + 1) << 7) >> 1;
    const int tid = threadIdx.x;

    float2 v[4];
    float m = -CUDART_INF_F;
    #pragma unroll
    for (int j = 0; j < 4; ++j) {
        int i = tid + j * 256;
        if (i < L2) { v[j] = row2[i]; m = fmaxf(m, fmaxf(v[j].x, v[j].y)); }
        else        { v[j] = make_float2(-CUDART_INF_F, -CUDART_INF_F); }
    }
    #pragma unroll
    for (int o = 16; o > 0; o >>= 1) m = fmaxf(m, __shfl_xor_sync(0xFFFFFFFFu, m, o));
    __shared__ float red[8];
    if ((tid & 31) == 0) red[tid >> 5] = m;
    __syncthreads();
    float mg = red[0];
    #pragma unroll
    for (int j = 1; j < 8; ++j) mg = fmaxf(mg, red[j]);
    __syncthreads();

    float sum = 0.f;
    #pragma unroll
    for (int j = 0; j < 4; ++j) {
        int i = tid + j * 256;
        if (i < L2) {
            v[j].x = __expf(v[j].x - mg);
            v[j].y = __expf(v[j].y - mg);
            sum += v[j].x + v[j].y;
        }
    }
    #pragma unroll
    for (int o = 16; o > 0; o >>= 1) sum += __shfl_xor_sync(0xFFFFFFFFu, sum, o);
    if ((tid & 31) == 0) red[tid >> 5] = sum;
    __syncthreads();
    float tot = 0.f;
    #pragma unroll
    for (int j = 0; j < 8; ++j) tot += red[j];
    float inv = 1.0f / tot;

    __nv_bfloat162* ph2 = reinterpret_cast<__nv_bfloat162*>(g_ph + off);
    __nv_bfloat162* pl2 = reinterpret_cast<__nv_bfloat162*>(g_pl + off);
    #pragma unroll
    for (int j = 0; j < 4; ++j) {
        int i = tid + j * 256;
        if (i < L2) {
            float p0 = v[j].x * inv, p1 = v[j].y * inv;
            bf16 h0 = __float2bfloat16(p0); bf16 l0 = __float2bfloat16(p0 - __bfloat162float(h0));
            bf16 h1 = __float2bfloat16(p1); bf16 l1 = __float2bfloat16(p1 - __bfloat162float(h1));
            ph2[i] = __halves2bfloat162(h0, h1);
            pl2[i] = __halves2bfloat162(l0, l1);
        }
    }
}

// ---------------------------------------------------------------------------
// PV (all batches) with split-K; grid (8 bx, B, 24 order).
// ---------------------------------------------------------------------------
__global__ __launch_bounds__(NTHR, 2)
void tc_pv_kernel(float* __restrict__ out)
{
    const int bx = blockIdx.x;
    const int b  = blockIdx.y;
    const int o  = blockIdx.z;
    const int by = d_pv_by[o];
    const int piece = d_pv_piece[o];

    extern __shared__ char smem[];
    uint32_t sb = smem_u32(smem);

    const int total = (by + 1) * 4;
    int niter, k0i;
    if (piece < 0) { niter = total;      k0i = 0; }
    else           { niter = total >> 1; k0i = piece ? niter : 0; }
    const int k0 = k0i * 32;

    size_t aoff = (size_t)b * S_ * S_ + (size_t)by * 128 * S_ + k0;
    size_t boff = (size_t)b * S_ * D_ + (size_t)bx * 128 + (size_t)k0 * D_;

    float acc[4][4][4];
    gemm_run<1>(sb, g_ph + aoff, g_pl + aoff, S_,
                    g_vh + boff, g_vl + boff, D_, niter, acc);

    const int tid = threadIdx.x, lane = tid & 31, wid = tid >> 5;
    const int wm = wid & 1, wn = wid >> 1;

    if (piece == 0) {
        const int sidx = (by - 8) + 8 * (bx + 8 * b);
        epi_f32_tile(acc, g_s + (size_t)sidx * 16384);
    } else {
        #pragma unroll
        for (int mi = 0; mi < 4; ++mi)
            #pragma unroll
            for (int ni = 0; ni < 4; ++ni) {
                int r0 = by * 128 + wm * 64 + mi * 16 + (lane >> 2);
                int c0 = bx * 128 + wn * 32 + ni * 8 + (lane & 3) * 2;
                #pragma unroll
                for (int half = 0; half < 2; ++half) {
                    int gq = r0 + half * 8;
                    *reinterpret_cast<float2*>(out + ((size_t)(b * S_ + gq)) * D_ + c0) =
                        make_float2(acc[mi][ni][half * 2 + 0], acc[mi][ni][half * 2 + 1]);
                }
            }
    }
}

// Add the 256 lower-half partials into out. Deterministic (plain adds).
__global__ __launch_bounds__(256)
void pv_combine_kernel(float* __restrict__ out)
{
    const int tile = blockIdx.x;
    const int b  = tile >> 6;
    const int bx = (tile >> 3) & 7;
    const int by = (tile & 7) + 8;
    const float4* src = reinterpret_cast<const float4*>(g_s + (size_t)tile * 16384);
    const int tid = threadIdx.x;
    #pragma unroll
    for (int j = 0; j < 16; ++j) {
        int f4 = j * 256 + tid;
        int r  = f4 >> 5;
        int c4 = f4 & 31;
        float4 s = src[f4];
        float4* op = reinterpret_cast<float4*>(
            out + ((size_t)(b * S_ + by * 128 + r)) * D_ + bx * 128 + c4 * 4);
        float4 v = *op;
        v.x += s.x; v.y += s.y; v.z += s.z; v.w += s.w;
        *op = v;
    }
}

// ---------------------------------------------------------------------------
extern "C" void kernel_launch(void* const* d_in, const int* in_sizes, int n_in,
                              void* d_out, int out_size)
{
    const float* x  = (const float*)d_in[0];
    const float* wq = (const float*)d_in[1];
    const float* wk = (const float*)d_in[2];
    const float* wv = (const float*)d_in[3];
    float* out = (float*)d_out;

    bf16 *xh, *xl, *wqh, *wql, *wkh, *wkl, *wvh, *wvl;
    cudaGetSymbolAddress((void**)&xh,  g_xh);  cudaGetSymbolAddress((void**)&xl,  g_xl);
    cudaGetSymbolAddress((void**)&wqh, g_wqh); cudaGetSymbolAddress((void**)&wql, g_wql);
    cudaGetSymbolAddress((void**)&wkh, g_wkh); cudaGetSymbolAddress((void**)&wkl, g_wkl);
    cudaGetSymbolAddress((void**)&wvh, g_wvh); cudaGetSymbolAddress((void**)&wvl, g_wvl);

    static bool attr_done = false;
    if (!attr_done) {
        cudaFuncSetAttribute(tc_projqk_kernel, cudaFuncAttributeMaxDynamicSharedMemorySize, SMEM_TOTAL);
        cudaFuncSetAttribute(tc_sv_kernel,     cudaFuncAttributeMaxDynamicSharedMemorySize, SMEM_TOTAL);
        cudaFuncSetAttribute(tc_pv_kernel,     cudaFuncAttributeMaxDynamicSharedMemorySize, SMEM_TOTAL);
        attr_done = true;
    }

    // Splits with tight grids (no idle blocks)
    split_x_kernel<<<M_ * D_ / 4 / 256, 256>>>((const float4*)x,
        (__nv_bfloat162*)xh, (__nv_bfloat162*)xl);
    {
        dim3 gw(D_ * D_ / 4 / 256, 3);
        split_w_kernel<<<gw, 256>>>((const float4*)wq, (const float4*)wk, (const float4*)wv,
            (__nv_bfloat162*)wqh, (__nv_bfloat162*)wql,
            (__nv_bfloat162*)wkh, (__nv_bfloat162*)wkl,
            (__nv_bfloat162*)wvh, (__nv_bfloat162*)wvl);
    }

    // Q+K projections: 912 fulls (3 exact waves) + 224 tail halves
    tc_projqk_kernel<<<1136, NTHR, SMEM_TOTAL>>>(xh, xl);
    qk_combine_kernel<<<112, 256>>>();

    // Merged scores + V projection: 912 fulls (3 exact waves) + 288 halves
    tc_sv_kernel<<<1200, NTHR, SMEM_TOTAL>>>();
    v_combine_kernel<<<144, 256>>>();

    // Softmax + P split
    dim3 gsm(S_, B_);
    softmax_split_kernel<<<gsm, 256>>>();

    // P @ V with split-K (descending work order), then combine partials
    dim3 gpv(D_ / 128, B_, 24);
    tc_pv_kernel<<<gpv, NTHR, SMEM_TOTAL>>>(out);
    pv_combine_kernel<<<256, 256>>>(out);
}

// round 17
// speedup vs baseline: 1.7809x; 1.0192x over previous
#include <cuda_runtime.h>
#include <cuda_bf16.h>
#include <cstdint>
#include <math.h>
#include <math_constants.h>

#define B_ 4
#define S_ 2048
#define D_ 1024
#define M_ (B_*S_)   // 8192

typedef __nv_bfloat16 bf16;

// ---------------------------------------------------------------------------
// Scratch (__device__ globals; allocation-free)
// ---------------------------------------------------------------------------
__device__ __align__(256) bf16 g_xh[M_*D_], g_xl[M_*D_];
__device__ __align__(256) bf16 g_wqh[D_*D_], g_wql[D_*D_];
__device__ __align__(256) bf16 g_wkh[D_*D_], g_wkl[D_*D_];
__device__ __align__(256) bf16 g_wvh[D_*D_], g_wvl[D_*D_];
__device__ __align__(256) bf16 g_qh[M_*D_], g_ql[M_*D_];
__device__ __align__(256) bf16 g_kh[M_*D_], g_kl[M_*D_];
__device__ __align__(256) bf16 g_vh[M_*D_], g_vl[M_*D_];      // V natural [b][s][d]
__device__ __align__(256) float g_s[(size_t)B_*S_*S_];        // scores; then PV split-K partials
__device__ __align__(256) bf16 g_ph[(size_t)B_*S_*S_], g_pl[(size_t)B_*S_*S_];
// Proj split-K fp32 partials live in g_ph (dead until softmax writes it).

// PV schedule: 24 entries per (b,bx), descending niter for work-steal packing.
__device__ const int d_pv_by[24]    = {15,15,7,14,14,13,13,6,12,12,11,11,5,10,10,9,9,4,8,8,3,2,1,0};
__device__ const int d_pv_piece[24] = { 0, 1,-1, 0, 1, 0, 1,-1, 0, 1, 0, 1,-1, 0, 1,0,1,-1,0,1,-1,-1,-1,-1};

// ---------------------------------------------------------------------------
#define LDBT_S 136
#define STG 33792u
#define OFF_AH(s) ((s)*STG)
#define OFF_AL(s) ((s)*STG + 8192u)
#define OFF_BH(s) ((s)*STG + 16384u)
#define OFF_BL(s) ((s)*STG + 25088u)
#define SMEM_TOTAL (3*33792)
#define NTHR 256

__device__ __forceinline__ uint32_t swz(int r, int k) {
    return (uint32_t)(r * 64 + ((((k >> 3) ^ ((r >> 1) & 3)) << 4) | ((k & 7) << 1)));
}
__device__ __forceinline__ uint32_t smem_u32(const void* p) {
    uint32_t a;
    asm("{ .reg .u64 t; cvta.to.shared.u64 t, %1; cvt.u32.u64 %0, t; }" : "=r"(a) : "l"(p));
    return a;
}
__device__ __forceinline__ void cpa16(uint32_t s, const void* g) {
    asm volatile("cp.async.cg.shared.global [%0], [%1], 16;" :: "r"(s), "l"(g));
}
__device__ __forceinline__ void ldm_x4(uint32_t addr, uint32_t r[4]) {
    asm volatile("ldmatrix.sync.aligned.m8n8.x4.shared.b16 {%0,%1,%2,%3}, [%4];"
        : "=r"(r[0]), "=r"(r[1]), "=r"(r[2]), "=r"(r[3]) : "r"(addr));
}
__device__ __forceinline__ void ldm_x4_t(uint32_t addr, uint32_t r[4]) {
    asm volatile("ldmatrix.sync.aligned.m8n8.x4.trans.shared.b16 {%0,%1,%2,%3}, [%4];"
        : "=r"(r[0]), "=r"(r[1]), "=r"(r[2]), "=r"(r[3]) : "r"(addr));
}
__device__ __forceinline__ void mma16816(float c[4], const uint32_t a[4], const uint32_t b[2]) {
    asm volatile("mma.sync.aligned.m16n8k16.row.col.f32.bf16.bf16.f32 "
        "{%0,%1,%2,%3}, {%4,%5,%6,%7}, {%8,%9}, {%0,%1,%2,%3};"
        : "+f"(c[0]), "+f"(c[1]), "+f"(c[2]), "+f"(c[3])
        : "r"(a[0]), "r"(a[1]), "r"(a[2]), "r"(a[3]), "r"(b[0]), "r"(b[1]));
}

// ---------------------------------------------------------------------------
template<int BT>
__device__ __forceinline__ void load_stage(uint32_t sb, int st, int tid,
    const bf16* __restrict__ Ah, const bf16* __restrict__ Al, int lda,
    const bf16* __restrict__ Bh, const bf16* __restrict__ Bl, int ldb, int k0)
{
    #pragma unroll
    for (int it = 0; it < 2; ++it) {
        int c = tid + it * NTHR;
        int row = c >> 2;
        int kc  = (c & 3) << 3;
        uint32_t so = swz(row, kc);
        cpa16(sb + OFF_AH(st) + so, Ah + (size_t)row * lda + k0 + kc);
        cpa16(sb + OFF_AL(st) + so, Al + (size_t)row * lda + k0 + kc);
        if (BT == 0) {
            cpa16(sb + OFF_BH(st) + so, Bh + (size_t)row * ldb + k0 + kc);
            cpa16(sb + OFF_BL(st) + so, Bl + (size_t)row * ldb + k0 + kc);
        } else {
            int br = c >> 4;
            int bn = (c & 15) << 3;
            uint32_t bo = (uint32_t)((br * LDBT_S + bn) * 2);
            cpa16(sb + OFF_BH(st) + bo, Bh + (size_t)(k0 + br) * ldb + bn);
            cpa16(sb + OFF_BL(st) + bo, Bl + (size_t)(k0 + br) * ldb + bn);
        }
    }
}

template<int BT>
__device__ __forceinline__ void compute_stage(uint32_t sb, int st, int lane,
                                              int wm, int wn, float acc[4][4][4])
{
    const uint32_t sAh = sb + OFF_AH(st), sAl = sb + OFF_AL(st);
    const uint32_t sBh = sb + OFF_BH(st), sBl = sb + OFF_BL(st);

    #pragma unroll
    for (int ks = 0; ks < 2; ++ks) {
        uint32_t bh[4][2], bl[4][2];
        if (BT == 0) {
            int nr = (lane & 7) + ((lane >> 4) & 1) * 8;
            int kh = ks * 16 + ((lane >> 3) & 1) * 8;
            #pragma unroll
            for (int np = 0; np < 2; ++np) {
                uint32_t off = swz(wn * 32 + np * 16 + nr, kh);
                uint32_t r[4];
                ldm_x4(sBh + off, r);
                bh[2*np][0]=r[0]; bh[2*np][1]=r[1]; bh[2*np+1][0]=r[2]; bh[2*np+1][1]=r[3];
                ldm_x4(sBl + off, r);
                bl[2*np][0]=r[0]; bl[2*np][1]=r[1]; bl[2*np+1][0]=r[2]; bl[2*np+1][1]=r[3];
            }
        } else {
            int kr = ks * 16 + ((lane >> 3) & 1) * 8 + (lane & 7);
            int nh = ((lane >> 4) & 1) * 8;
            #pragma unroll
            for (int np = 0; np < 2; ++np) {
                uint32_t off = (uint32_t)((kr * LDBT_S + wn * 32 + np * 16 + nh) * 2);
                uint32_t r[4];
                ldm_x4_t(sBh + off, r);
                bh[2*np][0]=r[0]; bh[2*np][1]=r[1]; bh[2*np+1][0]=r[2]; bh[2*np+1][1]=r[3];
                ldm_x4_t(sBl + off, r);
                bl[2*np][0]=r[0]; bl[2*np][1]=r[1]; bl[2*np+1][0]=r[2]; bl[2*np+1][1]=r[3];
            }
        }

        const int arow = wm * 64 + (lane & 15);
        const int akh  = ks * 16 + (lane >> 4) * 8;
        #pragma unroll
        for (int mi = 0; mi < 4; ++mi) {
            uint32_t ah[4], al[4];
            uint32_t off = swz(arow + mi * 16, akh);
            ldm_x4(sAh + off, ah);
            ldm_x4(sAl + off, al);
            #pragma unroll
            for (int ni = 0; ni < 4; ++ni) {
                mma16816(acc[mi][ni], ah, bh[ni]);
                mma16816(acc[mi][ni], ah, bl[ni]);
                mma16816(acc[mi][ni], al, bh[ni]);
            }
        }
    }
}

// 3-stage pipelined mainloop; one __syncthreads per iteration. niter >= 2.
template<int BT>
__device__ __forceinline__ void gemm_run(uint32_t sb,
    const bf16* __restrict__ Ah, const bf16* __restrict__ Al, int lda,
    const bf16* __restrict__ Bh, const bf16* __restrict__ Bl, int ldb,
    int niter, float acc[4][4][4])
{
    const int tid = threadIdx.x, lane = tid & 31, wid = tid >> 5;
    const int wm = wid & 1, wn = wid >> 1;

    #pragma unroll
    for (int mi = 0; mi < 4; ++mi)
        #pragma unroll
        for (int ni = 0; ni < 4; ++ni)
            #pragma unroll
            for (int j = 0; j < 4; ++j) acc[mi][ni][j] = 0.f;

    load_stage<BT>(sb, 0, tid, Ah, Al, lda, Bh, Bl, ldb, 0);
    asm volatile("cp.async.commit_group;" ::: "memory");
    load_stage<BT>(sb, 1, tid, Ah, Al, lda, Bh, Bl, ldb, 32);
    asm volatile("cp.async.commit_group;" ::: "memory");

    int st = 0;
    for (int i = 0; i < niter; ++i) {
        if (i + 1 < niter) asm volatile("cp.async.wait_group 1;" ::: "memory");
        else               asm volatile("cp.async.wait_group 0;" ::: "memory");
        __syncthreads();
        if (i + 2 < niter) {
            int slot = st + 2 >= 3 ? st - 1 : st + 2;
            load_stage<BT>(sb, slot, tid, Ah, Al, lda, Bh, Bl, ldb, (i + 2) * 32);
            asm volatile("cp.async.commit_group;" ::: "memory");
        }
        compute_stage<BT>(sb, st, lane, wm, wn, acc);
        st = (st == 2) ? 0 : st + 1;
    }
}

// Shared epilogue helpers ----------------------------------------------------
__device__ __forceinline__ void epi_bf16_split(float acc[4][4][4], int by, int bx,
                                               bf16* Oh, bf16* Ol)
{
    const int tid = threadIdx.x, lane = tid & 31, wid = tid >> 5;
    const int wm = wid & 1, wn = wid >> 1;
    #pragma unroll
    for (int mi = 0; mi < 4; ++mi)
        #pragma unroll
        for (int ni = 0; ni < 4; ++ni) {
            int r0 = by * 128 + wm * 64 + mi * 16 + (lane >> 2);
            int c0 = bx * 128 + wn * 32 + ni * 8 + (lane & 3) * 2;
            #pragma unroll
            for (int half = 0; half < 2; ++half) {
                int gr = r0 + half * 8;
                float v0 = acc[mi][ni][half * 2 + 0];
                float v1 = acc[mi][ni][half * 2 + 1];
                bf16 h0 = __float2bfloat16(v0); bf16 l0 = __float2bfloat16(v0 - __bfloat162float(h0));
                bf16 h1 = __float2bfloat16(v1); bf16 l1 = __float2bfloat16(v1 - __bfloat162float(h1));
                *reinterpret_cast<__nv_bfloat162*>(Oh + (size_t)gr * D_ + c0) = __halves2bfloat162(h0, h1);
                *reinterpret_cast<__nv_bfloat162*>(Ol + (size_t)gr * D_ + c0) = __halves2bfloat162(l0, l1);
            }
        }
}

__device__ __forceinline__ void epi_f32_tile(float acc[4][4][4], float* dst)
{
    const int tid = threadIdx.x, lane = tid & 31, wid = tid >> 5;
    const int wm = wid & 1, wn = wid >> 1;
    #pragma unroll
    for (int mi = 0; mi < 4; ++mi)
        #pragma unroll
        for (int ni = 0; ni < 4; ++ni) {
            int rl = wm * 64 + mi * 16 + (lane >> 2);
            int cl = wn * 32 + ni * 8 + (lane & 3) * 2;
            #pragma unroll
            for (int half = 0; half < 2; ++half)
                *reinterpret_cast<float2*>(dst + (rl + half * 8) * 128 + cl) =
                    make_float2(acc[mi][ni][half * 2 + 0], acc[mi][ni][half * 2 + 1]);
        }
}

// ---------------------------------------------------------------------------
// fp32 -> bf16 hi/lo splits. Tight grids.
// ---------------------------------------------------------------------------
__device__ __forceinline__ void split4(const float4 v, __nv_bfloat162* hi,
                                       __nv_bfloat162* lo, int i)
{
    bf16 h0 = __float2bfloat16(v.x); bf16 l0 = __float2bfloat16(v.x - __bfloat162float(h0));
    bf16 h1 = __float2bfloat16(v.y); bf16 l1 = __float2bfloat16(v.y - __bfloat162float(h1));
    bf16 h2 = __float2bfloat16(v.z); bf16 l2 = __float2bfloat16(v.z - __bfloat162float(h2));
    bf16 h3 = __float2bfloat16(v.w); bf16 l3 = __float2bfloat16(v.w - __bfloat162float(h3));
    hi[2*i]   = __halves2bfloat162(h0, h1);
    hi[2*i+1] = __halves2bfloat162(h2, h3);
    lo[2*i]   = __halves2bfloat162(l0, l1);
    lo[2*i+1] = __halves2bfloat162(l2, l3);
}

__global__ __launch_bounds__(256)
void split_x_kernel(const float4* __restrict__ x,
                    __nv_bfloat162* __restrict__ xh, __nv_bfloat162* __restrict__ xl)
{
    int i = blockIdx.x * 256 + threadIdx.x;
    split4(x[i], xh, xl, i);
}

__global__ __launch_bounds__(256)
void split_w_kernel(const float4* __restrict__ wq, const float4* __restrict__ wk,
                    const float4* __restrict__ wv,
                    __nv_bfloat162* __restrict__ wqh, __nv_bfloat162* __restrict__ wql,
                    __nv_bfloat162* __restrict__ wkh, __nv_bfloat162* __restrict__ wkl,
                    __nv_bfloat162* __restrict__ wvh, __nv_bfloat162* __restrict__ wvl)
{
    const int t = blockIdx.y;
    const float4* in; __nv_bfloat162 *hi, *lo;
    if (t == 0)      { in = wq; hi = wqh; lo = wql; }
    else if (t == 1) { in = wk; hi = wkh; lo = wkl; }
    else             { in = wv; hi = wvh; lo = wvl; }
    int i = blockIdx.x * 256 + threadIdx.x;
    split4(in[i], hi, lo, i);
}

// ---------------------------------------------------------------------------
// Q+K projection. Grid 1136: id<912 full tile; id>=912: 224 k-half pieces of
// K tiles 400..511 -> fp32 partials in g_ph.
// ---------------------------------------------------------------------------
__global__ __launch_bounds__(NTHR, 2)
void tc_projqk_kernel(const bf16* __restrict__ Ah, const bf16* __restrict__ Al)
{
    extern __shared__ char smem[];
    uint32_t sb = smem_u32(smem);
    const int id = blockIdx.x;

    int tile, niter, k0e, piece;
    if (id < 912) { tile = id; niter = 32; k0e = 0; piece = -1; }
    else { int p = id - 912; tile = 912 + (p >> 1); niter = 16; k0e = (p & 1) * 512; piece = p; }
    const int z = tile >> 9, by = (tile >> 3) & 63, bx = tile & 7;

    const bf16 *Bh = (z == 0) ? g_wqh : g_wkh;
    const bf16 *Bl = (z == 0) ? g_wql : g_wkl;

    float acc[4][4][4];
    gemm_run<0>(sb,
        Ah + (size_t)by * 128 * D_ + k0e, Al + (size_t)by * 128 * D_ + k0e, D_,
        Bh + (size_t)bx * 128 * D_ + k0e, Bl + (size_t)bx * 128 * D_ + k0e, D_,
        niter, acc);

    if (piece < 0) {
        epi_bf16_split(acc, by, bx, (z == 0) ? g_qh : g_kh, (z == 0) ? g_ql : g_kl);
    } else {
        epi_f32_tile(acc, reinterpret_cast<float*>(g_ph) + (size_t)piece * 16384);
    }
}

// Combine 224 K half-partials into K hi/lo. Quarter-tile blocks: grid 448.
__global__ __launch_bounds__(256)
void qk_combine_kernel()
{
    const int blk = blockIdx.x;            // [0,448)
    const int t   = blk >> 2;              // tile [0,112)
    const int q4  = blk & 3;               // row-quarter
    const int tile = 912 + t;
    const int by = (tile >> 3) & 63, bx = tile & 7;
    const float* scr = reinterpret_cast<const float*>(g_ph);
    const float4* p0 = reinterpret_cast<const float4*>(scr + (size_t)(2*t)   * 16384) + q4 * 1024;
    const float4* p1 = reinterpret_cast<const float4*>(scr + (size_t)(2*t+1) * 16384) + q4 * 1024;
    const int tid = threadIdx.x;

    #pragma unroll
    for (int j = 0; j < 4; ++j) {
        int f4 = j * 256 + tid;            // [0,1024)
        int r  = q4 * 32 + (f4 >> 5);
        int c4 = f4 & 31;
        float4 a = p0[f4], b = p1[f4];
        float v[4] = {a.x + b.x, a.y + b.y, a.z + b.z, a.w + b.w};
        size_t base = (size_t)(by * 128 + r) * D_ + bx * 128 + c4 * 4;
        #pragma unroll
        for (int e = 0; e < 4; e += 2) {
            bf16 h0 = __float2bfloat16(v[e]);   bf16 l0 = __float2bfloat16(v[e]   - __bfloat162float(h0));
            bf16 h1 = __float2bfloat16(v[e+1]); bf16 l1 = __float2bfloat16(v[e+1] - __bfloat162float(h1));
            *reinterpret_cast<__nv_bfloat162*>(g_kh + base + e) = __halves2bfloat162(h0, h1);
            *reinterpret_cast<__nv_bfloat162*>(g_kl + base + e) = __halves2bfloat162(l0, l1);
        }
    }
}

// ---------------------------------------------------------------------------
// Merged scores + V-projection. Grid 1200 (544 scores + 368 V fulls + 288 halves).
// ---------------------------------------------------------------------------
__global__ __launch_bounds__(NTHR, 2)
void tc_sv_kernel()
{
    extern __shared__ char smem[];
    uint32_t sb = smem_u32(smem);
    const int id = blockIdx.x;

    if (id < 544) {
        const int b = id / 136;
        const int idx = id % 136;
        int by = (int)((sqrtf(8.f * idx + 1.f) - 1.f) * 0.5f);
        while ((by + 1) * (by + 2) / 2 <= idx) ++by;
        while (by * (by + 1) / 2 > idx) --by;
        const int bx = idx - by * (by + 1) / 2;

        size_t aoff = ((size_t)b * S_ + by * 128) * D_;
        size_t boff = ((size_t)b * S_ + bx * 128) * D_;
        float acc[4][4][4];
        gemm_run<0>(sb, g_qh + aoff, g_ql + aoff, D_,
                        g_kh + boff, g_kl + boff, D_, D_ / 32, acc);

        const int tid = threadIdx.x, lane = tid & 31, wid = tid >> 5;
        const int wm = wid & 1, wn = wid >> 1;
        const bool diag = (bx == by);
        const float alpha = 0.03125f;
        float* out = g_s + (size_t)b * S_ * S_;
        #pragma unroll
        for (int mi = 0; mi < 4; ++mi)
            #pragma unroll
            for (int ni = 0; ni < 4; ++ni) {
                int r0 = by * 128 + wm * 64 + mi * 16 + (lane >> 2);
                int c0 = bx * 128 + wn * 32 + ni * 8 + (lane & 3) * 2;
                #pragma unroll
                for (int half = 0; half < 2; ++half) {
                    int gr = r0 + half * 8;
                    float s0 = acc[mi][ni][half * 2 + 0] * alpha;
                    float s1 = acc[mi][ni][half * 2 + 1] * alpha;
                    if (diag) {
                        if (c0 > gr)     s0 = -CUDART_INF_F;
                        if (c0 + 1 > gr) s1 = -CUDART_INF_F;
                    }
                    *reinterpret_cast<float2*>(out + (size_t)gr * S_ + c0) = make_float2(s0, s1);
                }
            }
    } else {
        int vt, niter, k0e, piece;
        if (id < 912) { vt = id - 544; niter = 32; k0e = 0; piece = -1; }
        else { int p = id - 912; vt = 368 + (p >> 1); niter = 16; k0e = (p & 1) * 512; piece = p; }
        const int by = vt >> 3, bx = vt & 7;

        float acc[4][4][4];
        gemm_run<0>(sb,
            g_xh + (size_t)by * 128 * D_ + k0e, g_xl + (size_t)by * 128 * D_ + k0e, D_,
            g_wvh + (size_t)bx * 128 * D_ + k0e, g_wvl + (size_t)bx * 128 * D_ + k0e, D_,
            niter, acc);

        if (piece < 0) epi_bf16_split(acc, by, bx, g_vh, g_vl);
        else epi_f32_tile(acc, reinterpret_cast<float*>(g_ph) + (size_t)piece * 16384);
    }
}

// Combine 288 V half-partials into V hi/lo. Quarter-tile blocks: grid 576.
__global__ __launch_bounds__(256)
void v_combine_kernel()
{
    const int blk = blockIdx.x;            // [0,576)
    const int t   = blk >> 2;              // [0,144)
    const int q4  = blk & 3;
    const int vt = 368 + t;
    const int by = vt >> 3, bx = vt & 7;
    const float* scr = reinterpret_cast<const float*>(g_ph);
    const float4* p0 = reinterpret_cast<const float4*>(scr + (size_t)(2*t)   * 16384) + q4 * 1024;
    const float4* p1 = reinterpret_cast<const float4*>(scr + (size_t)(2*t+1) * 16384) + q4 * 1024;
    const int tid = threadIdx.x;
    #pragma unroll
    for (int j = 0; j < 4; ++j) {
        int f4 = j * 256 + tid;
        int r  = q4 * 32 + (f4 >> 5);
        int c4 = f4 & 31;
        float4 a = p0[f4], b = p1[f4];
        float v[4] = {a.x + b.x, a.y + b.y, a.z + b.z, a.w + b.w};
        size_t base = (size_t)(by * 128 + r) * D_ + bx * 128 + c4 * 4;
        #pragma unroll
        for (int e = 0; e < 4; e += 2) {
            bf16 h0 = __float2bfloat16(v[e]);   bf16 l0 = __float2bfloat16(v[e]   - __bfloat162float(h0));
            bf16 h1 = __float2bfloat16(v[e+1]); bf16 l1 = __float2bfloat16(v[e+1] - __bfloat162float(h1));
            *reinterpret_cast<__nv_bfloat162*>(g_vh + base + e) = __halves2bfloat162(h0, h1);
            *reinterpret_cast<__nv_bfloat162*>(g_vl + base + e) = __halves2bfloat162(l0, l1);
        }
    }
}

// ---------------------------------------------------------------------------
// Softmax over causal prefix; float2 in, bf16x2 h/l out.
// ---------------------------------------------------------------------------
__global__ __launch_bounds__(256)
void softmax_split_kernel()
{
    const int q = blockIdx.x;
    const int b = blockIdx.y;
    const size_t off = (size_t)b * S_ * S_ + (size_t)q * S_;
    const float2* row2 = reinterpret_cast<const float2*>(g_s + off);
    const int L2 = (((q >> 7) + 1) << 7) >> 1;
    const int tid = threadIdx.x;

    float2 v[4];
    float m = -CUDART_INF_F;
    #pragma unroll
    for (int j = 0; j < 4; ++j) {
        int i = tid + j * 256;
        if (i < L2) { v[j] = row2[i]; m = fmaxf(m, fmaxf(v[j].x, v[j].y)); }
        else        { v[j] = make_float2(-CUDART_INF_F, -CUDART_INF_F); }
    }
    #pragma unroll
    for (int o = 16; o > 0; o >>= 1) m = fmaxf(m, __shfl_xor_sync(0xFFFFFFFFu, m, o));
    __shared__ float red[8];
    if ((tid & 31) == 0) red[tid >> 5] = m;
    __syncthreads();
    float mg = red[0];
    #pragma unroll
    for (int j = 1; j < 8; ++j) mg = fmaxf(mg, red[j]);
    __syncthreads();

    float sum = 0.f;
    #pragma unroll
    for (int j = 0; j < 4; ++j) {
        int i = tid + j * 256;
        if (i < L2) {
            v[j].x = __expf(v[j].x - mg);
            v[j].y = __expf(v[j].y - mg);
            sum += v[j].x + v[j].y;
        }
    }
    #pragma unroll
    for (int o = 16; o > 0; o >>= 1) sum += __shfl_xor_sync(0xFFFFFFFFu, sum, o);
    if ((tid & 31) == 0) red[tid >> 5] = sum;
    __syncthreads();
    float tot = 0.f;
    #pragma unroll
    for (int j = 0; j < 8; ++j) tot += red[j];
    float inv = 1.0f / tot;

    __nv_bfloat162* ph2 = reinterpret_cast<__nv_bfloat162*>(g_ph + off);
    __nv_bfloat162* pl2 = reinterpret_cast<__nv_bfloat162*>(g_pl + off);
    #pragma unroll
    for (int j = 0; j < 4; ++j) {
        int i = tid + j * 256;
        if (i < L2) {
            float p0 = v[j].x * inv, p1 = v[j].y * inv;
            bf16 h0 = __float2bfloat16(p0); bf16 l0 = __float2bfloat16(p0 - __bfloat162float(h0));
            bf16 h1 = __float2bfloat16(p1); bf16 l1 = __float2bfloat16(p1 - __bfloat162float(h1));
            ph2[i] = __halves2bfloat162(h0, h1);
            pl2[i] = __halves2bfloat162(l0, l1);
        }
    }
}

// ---------------------------------------------------------------------------
// PV (all batches) with split-K; grid (8 bx, B, 24 order).
// ---------------------------------------------------------------------------
__global__ __launch_bounds__(NTHR, 2)
void tc_pv_kernel(float* __restrict__ out)
{
    const int bx = blockIdx.x;
    const int b  = blockIdx.y;
    const int o  = blockIdx.z;
    const int by = d_pv_by[o];
    const int piece = d_pv_piece[o];

    extern __shared__ char smem[];
    uint32_t sb = smem_u32(smem);

    const int total = (by + 1) * 4;
    int niter, k0i;
    if (piece < 0) { niter = total;      k0i = 0; }
    else           { niter = total >> 1; k0i = piece ? niter : 0; }
    const int k0 = k0i * 32;

    size_t aoff = (size_t)b * S_ * S_ + (size_t)by * 128 * S_ + k0;
    size_t boff = (size_t)b * S_ * D_ + (size_t)bx * 128 + (size_t)k0 * D_;

    float acc[4][4][4];
    gemm_run<1>(sb, g_ph + aoff, g_pl + aoff, S_,
                    g_vh + boff, g_vl + boff, D_, niter, acc);

    const int tid = threadIdx.x, lane = tid & 31, wid = tid >> 5;
    const int wm = wid & 1, wn = wid >> 1;

    if (piece == 0) {
        const int sidx = (by - 8) + 8 * (bx + 8 * b);
        epi_f32_tile(acc, g_s + (size_t)sidx * 16384);
    } else {
        #pragma unroll
        for (int mi = 0; mi < 4; ++mi)
            #pragma unroll
            for (int ni = 0; ni < 4; ++ni) {
                int r0 = by * 128 + wm * 64 + mi * 16 + (lane >> 2);
                int c0 = bx * 128 + wn * 32 + ni * 8 + (lane & 3) * 2;
                #pragma unroll
                for (int half = 0; half < 2; ++half) {
                    int gq = r0 + half * 8;
                    *reinterpret_cast<float2*>(out + ((size_t)(b * S_ + gq)) * D_ + c0) =
                        make_float2(acc[mi][ni][half * 2 + 0], acc[mi][ni][half * 2 + 1]);
                }
            }
    }
}

// Add the 256 lower-half partials into out. Quarter-tile blocks: grid 1024.
__global__ __launch_bounds__(256)
void pv_combine_kernel(float* __restrict__ out)
{
    const int blk = blockIdx.x;             // [0,1024)
    const int tile = blk >> 2;              // sidx [0,256)
    const int q4   = blk & 3;
    const int b  = tile >> 6;
    const int bx = (tile >> 3) & 7;
    const int by = (tile & 7) + 8;
    const float4* src = reinterpret_cast<const float4*>(g_s + (size_t)tile * 16384) + q4 * 1024;
    const int tid = threadIdx.x;
    #pragma unroll
    for (int j = 0; j < 4; ++j) {
        int f4 = j * 256 + tid;             // [0,1024)
        int r  = q4 * 32 + (f4 >> 5);
        int c4 = f4 & 31;
        float4 s = src[f4];
        float4* op = reinterpret_cast<float4*>(
            out + ((size_t)(b * S_ + by * 128 + r)) * D_ + bx * 128 + c4 * 4);
        float4 v = *op;
        v.x += s.x; v.y += s.y; v.z += s.z; v.w += s.w;
        *op = v;
    }
}

// ---------------------------------------------------------------------------
extern "C" void kernel_launch(void* const* d_in, const int* in_sizes, int n_in,
                              void* d_out, int out_size)
{
    const float* x  = (const float*)d_in[0];
    const float* wq = (const float*)d_in[1];
    const float* wk = (const float*)d_in[2];
    const float* wv = (const float*)d_in[3];
    float* out = (float*)d_out;

    bf16 *xh, *xl, *wqh, *wql, *wkh, *wkl, *wvh, *wvl;
    cudaGetSymbolAddress((void**)&xh,  g_xh);  cudaGetSymbolAddress((void**)&xl,  g_xl);
    cudaGetSymbolAddress((void**)&wqh, g_wqh); cudaGetSymbolAddress((void**)&wql, g_wql);
    cudaGetSymbolAddress((void**)&wkh, g_wkh); cudaGetSymbolAddress((void**)&wkl, g_wkl);
    cudaGetSymbolAddress((void**)&wvh, g_wvh); cudaGetSymbolAddress((void**)&wvl, g_wvl);

    static bool attr_done = false;
    if (!attr_done) {
        cudaFuncSetAttribute(tc_projqk_kernel, cudaFuncAttributeMaxDynamicSharedMemorySize, SMEM_TOTAL);
        cudaFuncSetAttribute(tc_sv_kernel,     cudaFuncAttributeMaxDynamicSharedMemorySize, SMEM_TOTAL);
        cudaFuncSetAttribute(tc_pv_kernel,     cudaFuncAttributeMaxDynamicSharedMemorySize, SMEM_TOTAL);
        attr_done = true;
    }

    // Splits with tight grids
    split_x_kernel<<<M_ * D_ / 4 / 256, 256>>>((const float4*)x,
        (__nv_bfloat162*)xh, (__nv_bfloat162*)xl);
    {
        dim3 gw(D_ * D_ / 4 / 256, 3);
        split_w_kernel<<<gw, 256>>>((const float4*)wq, (const float4*)wk, (const float4*)wv,
            (__nv_bfloat162*)wqh, (__nv_bfloat162*)wql,
            (__nv_bfloat162*)wkh, (__nv_bfloat162*)wkl,
            (__nv_bfloat162*)wvh, (__nv_bfloat162*)wvl);
    }

    // Q+K projections: 912 fulls (3 exact waves) + 224 tail halves
    tc_projqk_kernel<<<1136, NTHR, SMEM_TOTAL>>>(xh, xl);
    qk_combine_kernel<<<448, 256>>>();

    // Merged scores + V projection: 912 fulls (3 exact waves) + 288 halves
    tc_sv_kernel<<<1200, NTHR, SMEM_TOTAL>>>();
    v_combine_kernel<<<576, 256>>>();

    // Softmax + P split
    dim3 gsm(S_, B_);
    softmax_split_kernel<<<gsm, 256>>>();

    // P @ V with split-K (descending work order), then combine partials
    dim3 gpv(D_ / 128, B_, 24);
    tc_pv_kernel<<<gpv, NTHR, SMEM_TOTAL>>>(out);
    pv_combine_kernel<<<1024, 256>>>(out);
}